// round 11
// baseline (speedup 1.0000x reference)
#include <cuda_runtime.h>
#include <cstdint>

using ull = unsigned long long;
#define FULL_MASK 0xFFFFFFFFu

constexpr int B_ = 2048;
constexpr int L_ = 2048;
constexpr float LOG2E_F = 1.4426950408889634f;
constexpr float LN2_F   = 0.6931471805599453f;

// device scratch (no allocation allowed)
__device__ int   g_len[B_], g_order[B_];
__device__ int   g_c1 = 0, g_c2 = 0;
__device__ __align__(16) float g_af[B_ * 8], g_w[B_ * 8];
__device__ __align__(16) float g_P2[B_ * 64], g_P3[B_ * 64];
__device__ __align__(16) float g_c2r[B_ * 8], g_c3r[B_ * 8];
__device__ float g_cf[B_], g_cb[B_];
__device__ float g_nf[B_], g_n1[B_], g_n2[B_], g_nb[B_];

#define PK2(d, lo, hi) asm("mov.b64 %0, {%1, %2};" : "=l"(d) : "f"(lo), "f"(hi))
#define UPK2(lo, hi, s) asm("mov.b64 {%0, %1}, %2;" : "=f"(lo), "=f"(hi) : "l"(s))
#define FMA2(d, a, b, c) asm("fma.rn.f32x2 %0, %1, %2, %3;" : "=l"(d) : "l"(a), "l"(b), "l"(c))
#define MUL2(d, a, b) asm("mul.rn.f32x2 %0, %1, %2;" : "=l"(d) : "l"(a), "l"(b))

__device__ __forceinline__ float fx2(float x)
{ float r; asm("ex2.approx.ftz.f32 %0, %1;" : "=f"(r) : "f"(x)); return r; }
__device__ __forceinline__ float fexp(float x) { return fx2(x * LOG2E_F); }
__device__ __forceinline__ void l2pf(const void* p)
{ asm volatile("prefetch.global.L2 [%0];" :: "l"(p)); }

// exp(em row) -> 4 packed f32x2
__device__ __forceinline__ void mk_ex2(float4 lo, float4 hi, ull X[4])
{
    float e0 = fexp(lo.x), e1 = fexp(lo.y), e2 = fexp(lo.z), e3 = fexp(lo.w);
    float e4 = fexp(hi.x), e5 = fexp(hi.y), e6 = fexp(hi.z), e7 = fexp(hi.w);
    PK2(X[0], e0, e1); PK2(X[1], e2, e3); PK2(X[2], e4, e5); PK2(X[3], e6, e7);
}

__device__ __forceinline__ void renorm8(float a[8], float& c)
{
    int eb = __float_as_int(a[0]) & 0x7f800000;
    c += (float)((eb >> 23) - 127);
    float s = __int_as_float(0x7f000000 - eb);      // exact 2^{-e}
    #pragma unroll
    for (int q = 0; q < 8; q++) a[q] *= s;
}

// row-vector recursion a <- (a · E) ⊙ ex_t, t = t0..t1 ascending.
// E2[k*4+p] = (E[k][2p], E[k][2p+1]).
__device__ __forceinline__ void chain_fwd(
    const float* __restrict__ emB, const int* __restrict__ tgB,
    const ull E2[32], const float* s_tr,
    int t0, int t1, bool donum, int s_prev,
    float a[8], float& c, float& num)
{
    const float4* rp0 = (const float4*)(emB + (size_t)t0 * 8);
    float4 lo = __ldg(rp0), hi = __ldg(rp0 + 1);
    ull X[4]; mk_ex2(lo, hi, X);
    int tagc = donum ? __ldg(&tgB[t0]) : 1;
    int rc = 8;
    #pragma unroll 2
    for (int t = t0; t <= t1; t++) {
        int tn = min(t + 1, t1);
        const float4* rp = (const float4*)(emB + (size_t)tn * 8);
        float4 nlo = __ldg(rp), nhi = __ldg(rp + 1);
        l2pf(emB + (size_t)min(t + 16, t1) * 8);
        ull b2, a0, a1, a2, a3;
        PK2(b2, a[0], a[0]);
        MUL2(a0, b2, E2[0]); MUL2(a1, b2, E2[1]); MUL2(a2, b2, E2[2]); MUL2(a3, b2, E2[3]);
        #pragma unroll
        for (int k = 1; k < 8; k++) {
            PK2(b2, a[k], a[k]);
            FMA2(a0, b2, E2[k * 4 + 0], a0); FMA2(a1, b2, E2[k * 4 + 1], a1);
            FMA2(a2, b2, E2[k * 4 + 2], a2); FMA2(a3, b2, E2[k * 4 + 3], a3);
        }
        MUL2(a0, a0, X[0]); MUL2(a1, a1, X[1]); MUL2(a2, a2, X[2]); MUL2(a3, a3, X[3]);
        UPK2(a[0], a[1], a0); UPK2(a[2], a[3], a1);
        UPK2(a[4], a[5], a2); UPK2(a[6], a[7], a3);
        if (donum) {
            int st = tagc - 1;
            num += s_tr[(s_prev << 3) | st] + __ldg(emB + (size_t)t * 8 + st);
            s_prev = st;
            tagc = __ldg(&tgB[tn]);
        }
        if (--rc == 0) { rc = 8; renorm8(a, c); }
        mk_ex2(nlo, nhi, X);
    }
    renorm8(a, c);                                   // final renorm -> stored O(1)
}

// column-vector recursion w <- E · (ex_t ⊙ w), t = thi..tlo descending. Always numerator.
__device__ __forceinline__ void chain_bwd(
    const float* __restrict__ emB, const int* __restrict__ tgB,
    const ull E2[32], const float* s_tr, const float* __restrict__ endT,
    int thi, int tlo,
    float w[8], float& c, float& num)
{
    const float4* rp0 = (const float4*)(emB + (size_t)thi * 8);
    float4 lo = __ldg(rp0), hi = __ldg(rp0 + 1);
    ull X[4]; mk_ex2(lo, hi, X);
    int s_hi = __ldg(&tgB[thi]) - 1;
    num += __ldg(&endT[s_hi]);
    int rc = 8;
    #pragma unroll 2
    for (int t = thi; t >= tlo; t--) {
        int tn = max(t - 1, tlo);
        const float4* rp = (const float4*)(emB + (size_t)tn * 8);
        float4 nlo = __ldg(rp), nhi = __ldg(rp + 1);
        l2pf(emB + (size_t)max(t - 16, tlo) * 8);
        ull p0, p1, p2, p3;
        PK2(p0, w[0], w[1]); PK2(p1, w[2], w[3]); PK2(p2, w[4], w[5]); PK2(p3, w[6], w[7]);
        MUL2(p0, p0, X[0]); MUL2(p1, p1, X[1]); MUL2(p2, p2, X[2]); MUL2(p3, p3, X[3]);
        #pragma unroll
        for (int k = 0; k < 8; k++) {
            ull acc;
            MUL2(acc, p0, E2[k * 4 + 0]);
            FMA2(acc, p1, E2[k * 4 + 1], acc);
            FMA2(acc, p2, E2[k * 4 + 2], acc);
            FMA2(acc, p3, E2[k * 4 + 3], acc);
            float l, h; UPK2(l, h, acc);
            w[k] = l + h;
        }
        int sl = __ldg(&tgB[t - 1]) - 1;             // t-1 >= tlo-1 = q3 >= 768
        num += s_tr[(sl << 3) | s_hi] + __ldg(emB + (size_t)t * 8 + s_hi);
        s_hi = sl;
        if (--rc == 0) { rc = 8; renorm8(w, c); }
        mk_ex2(nlo, nhi, X);
    }
    renorm8(w, c);
}

// ---------------- kernel 1: lengths + counting-sort order (last block) ----------------
__global__ void crf_prep(const int* __restrict__ tags)
{
    int w    = blockIdx.x * 8 + (threadIdx.x >> 5);
    int lane = threadIdx.x & 31;
    const int4* p = (const int4*)(tags + (size_t)w * L_ + 1024);
    int firstz = 1024;
    #pragma unroll
    for (int k = 0; k < 8; k++) {
        int4 v = p[k * 32 + lane];
        int base = (k * 32 + lane) * 4;
        if (v.w == 0) firstz = min(firstz, base + 3);
        if (v.z == 0) firstz = min(firstz, base + 2);
        if (v.y == 0) firstz = min(firstz, base + 1);
        if (v.x == 0) firstz = min(firstz, base + 0);
    }
    firstz = __reduce_min_sync(FULL_MASK, firstz);
    if (lane == 0) g_len[w] = 1024 + firstz;

    __threadfence();
    __syncthreads();
    __shared__ int s_last;
    if (threadIdx.x == 0) s_last = atomicAdd(&g_c1, 1);
    __syncthreads();
    if (s_last == gridDim.x - 1) {
        __threadfence();
        __shared__ int hist[1025];
        for (int i = threadIdx.x; i < 1025; i += 256) hist[i] = 0;
        __syncthreads();
        for (int i = threadIdx.x; i < B_; i += 256)
            atomicAdd(&hist[__ldcg(&g_len[i]) - 1024], 1);
        __syncthreads();
        if (threadIdx.x == 0) {
            int run = 0;
            for (int k = 0; k < 1025; k++) { int t = hist[k]; hist[k] = run; run += t; }
            g_c1 = 0;
        }
        __syncthreads();
        for (int i = threadIdx.x; i < B_; i += 256) {
            int pos = atomicAdd(&hist[__ldcg(&g_len[i]) - 1024], 1);
            g_order[pos] = i;                        // bucket-internal order arbitrary: affects
        }                                            // only warp assignment, not output values
    }
}

// ---------------- kernel 2: all chains + fused combine ----------------
__global__ __launch_bounds__(128)
void crf_chains(const float* __restrict__ em, const float* __restrict__ trans,
                const float* __restrict__ startT, const float* __restrict__ endT,
                const int* __restrict__ tags, float* __restrict__ out)
{
    __shared__ float s_tr[64];
    __shared__ int   s_last;
    int tid = threadIdx.x;
    if (tid < 64) s_tr[tid] = trans[tid];
    __syncthreads();

    int lane = tid & 31;
    int gw   = blockIdx.x * 4 + (tid >> 5);          // 0..1151

    ull E2[32];
    #pragma unroll
    for (int k = 0; k < 8; k++)
        #pragma unroll
        for (int p = 0; p < 4; p++) {
            float e0 = fexp(s_tr[k * 8 + 2 * p]);
            float e1 = fexp(s_tr[k * 8 + 2 * p + 1]);
            PK2(E2[k * 4 + p], e0, e1);
        }

    float a[8], c = 0.0f, num = 0.0f;

    if (gw < 64) {
        // ---- forward vector chain: t in [1, q1] ----
        int b   = g_order[gw * 32 + lane];
        int len = g_len[b], q1 = len >> 2;
        const float* emB = em   + (size_t)b * (L_ * 8);
        const int*   tgB = tags + (size_t)b * L_;
        int s0 = __ldg(&tgB[0]) - 1;
        const float4* rp = (const float4*)emB;
        float4 lo = __ldg(rp), hi = __ldg(rp + 1);
        a[0] = fexp(startT[0] + lo.x); a[1] = fexp(startT[1] + lo.y);
        a[2] = fexp(startT[2] + lo.z); a[3] = fexp(startT[3] + lo.w);
        a[4] = fexp(startT[4] + hi.x); a[5] = fexp(startT[5] + hi.y);
        a[6] = fexp(startT[6] + hi.z); a[7] = fexp(startT[7] + hi.w);
        num = __ldg(&startT[s0]) + __ldg(emB + s0);
        chain_fwd(emB, tgB, E2, s_tr, 1, q1, true, s0, a, c, num);
        #pragma unroll
        for (int j = 0; j < 8; j++) g_af[b * 8 + j] = a[j];
        g_cf[b] = c; g_nf[b] = num;
    } else if (gw < 128) {
        // ---- backward vector chain: t in [q3+1, len-1] descending ----
        int b   = g_order[(gw - 64) * 32 + lane];
        int len = g_len[b], q3 = (3 * len) >> 2;
        const float* emB = em   + (size_t)b * (L_ * 8);
        const int*   tgB = tags + (size_t)b * L_;
        #pragma unroll
        for (int j = 0; j < 8; j++) a[j] = fexp(__ldg(&endT[j]));
        chain_bwd(emB, tgB, E2, s_tr, endT, len - 1, q3 + 1, a, c, num);
        #pragma unroll
        for (int j = 0; j < 8; j++) g_w[b * 8 + j] = a[j];
        g_cb[b] = c; g_nb[b] = num;
    } else {
        // ---- interior matrix segment: basis-row chains ----
        bool s2  = (gw >= 640);
        int  idx = gw - (s2 ? 640 : 128);
        int  b   = g_order[idx * 4 + (lane >> 3)];
        int  r   = lane & 7;
        int len = g_len[b];
        int q1 = len >> 2, q2 = len >> 1, q3 = (3 * len) >> 2;
        int t0 = (s2 ? q2 : q1) + 1, t1 = s2 ? q3 : q2;
        const float* emB = em   + (size_t)b * (L_ * 8);
        const int*   tgB = tags + (size_t)b * L_;
        #pragma unroll
        for (int j = 0; j < 8; j++) a[j] = (j == r) ? 1.0f : 0.0f;
        bool dn = (r == 0);
        int  sp = dn ? (__ldg(&tgB[t0 - 1]) - 1) : 0;
        chain_fwd(emB, tgB, E2, s_tr, t0, t1, dn, sp, a, c, num);
        float* P  = s2 ? g_P3  : g_P2;
        float* Cr = s2 ? g_c3r : g_c2r;
        #pragma unroll
        for (int j = 0; j < 8; j++) P[b * 64 + r * 8 + j] = a[j];
        Cr[b * 8 + r] = c;
        if (dn) { if (s2) g_n2[b] = num; else g_n1[b] = num; }
    }

    // ---- last block combines: Z = alpha · P2 · P3 · w, fixed-order mean ----
    __threadfence();
    __syncthreads();
    if (tid == 0) s_last = atomicAdd(&g_c2, 1);
    __syncthreads();
    if (s_last == gridDim.x - 1) {
        __threadfence();
        __shared__ float sb[128];
        float acc = 0.0f;
        #pragma unroll 1
        for (int it = 0; it < 16; it++) {
            int b = tid + it * 128;                  // fixed per-thread order
            float u[8], u2[8];
            #pragma unroll
            for (int j = 0; j < 8; j++) u[j] = __ldcg(&g_af[b * 8 + j]);
            float C = __ldcg(&g_cf[b]) + __ldcg(&g_cb[b]);
            // stage P2
            {
                float cr[8], m = -1e30f;
                #pragma unroll
                for (int r2 = 0; r2 < 8; r2++) { cr[r2] = __ldcg(&g_c2r[b * 8 + r2]); m = fmaxf(m, cr[r2]); }
                C += m;
                #pragma unroll
                for (int j = 0; j < 8; j++) u2[j] = 0.0f;
                #pragma unroll
                for (int r2 = 0; r2 < 8; r2++) {
                    int d = max((int)(cr[r2] - m), -120);
                    float ur = u[r2] * __int_as_float((127 + d) << 23);
                    #pragma unroll
                    for (int j = 0; j < 8; j++)
                        u2[j] = fmaf(ur, __ldcg(&g_P2[b * 64 + r2 * 8 + j]), u2[j]);
                }
            }
            // stage P3
            {
                float cr[8], m = -1e30f;
                #pragma unroll
                for (int r2 = 0; r2 < 8; r2++) { cr[r2] = __ldcg(&g_c3r[b * 8 + r2]); m = fmaxf(m, cr[r2]); }
                C += m;
                #pragma unroll
                for (int j = 0; j < 8; j++) u[j] = 0.0f;
                #pragma unroll
                for (int r2 = 0; r2 < 8; r2++) {
                    int d = max((int)(cr[r2] - m), -120);
                    float ur = u2[r2] * __int_as_float((127 + d) << 23);
                    #pragma unroll
                    for (int j = 0; j < 8; j++)
                        u[j] = fmaf(ur, __ldcg(&g_P3[b * 64 + r2 * 8 + j]), u[j]);
                }
            }
            float Z = 0.0f;
            #pragma unroll
            for (int j = 0; j < 8; j++) Z = fmaf(u[j], __ldcg(&g_w[b * 8 + j]), Z);
            float denom = LN2_F * (C + __log2f(Z));
            acc += __ldcg(&g_nf[b]) + __ldcg(&g_n1[b]) + __ldcg(&g_n2[b]) + __ldcg(&g_nb[b]) - denom;
        }
        sb[tid] = acc;
        __syncthreads();
        for (int k = 64; k > 0; k >>= 1) {
            if (tid < k) sb[tid] += sb[tid + k];
            __syncthreads();
        }
        if (tid == 0) { out[0] = -sb[0] * (1.0f / (float)B_); g_c2 = 0; }
    }
}

extern "C" void kernel_launch(void* const* d_in, const int* in_sizes, int n_in,
                              void* d_out, int out_size)
{
    const float* em    = (const float*)d_in[0];   // (B, L, T) f32
    const float* trans = (const float*)d_in[1];   // (T, T)    f32
    const float* st    = (const float*)d_in[2];   // (T,)      f32
    const float* en    = (const float*)d_in[3];   // (T,)      f32
    const int*   tags  = (const int*)  d_in[4];   // (B, L)    int32

    crf_prep  <<<256, 256>>>(tags);
    crf_chains<<<288, 128>>>(em, trans, st, en, tags, (float*)d_out);
}

// round 13
// speedup vs baseline: 1.5465x; 1.5465x over previous
#include <cuda_runtime.h>
#include <cstdint>

#define FULL_MASK 0xFFFFFFFFu

constexpr int B_ = 2048;
constexpr int L_ = 2048;
constexpr float LOG2E_F = 1.4426950408889634f;
constexpr float LN2_F   = 0.6931471805599453f;

// device scratch (no allocation allowed)
__device__ int g_len[B_], g_order[B_];
__device__ __align__(16) float g_af[B_ * 8], g_w[B_ * 8];
__device__ float g_cf[B_], g_cb[B_], g_nf[B_], g_nb[B_];

__device__ __forceinline__ float fx2(float x)
{ float r; asm("ex2.approx.ftz.f32 %0, %1;" : "=f"(r) : "f"(x)); return r; }
__device__ __forceinline__ float fexp(float x) { return fx2(x * LOG2E_F); }
__device__ __forceinline__ void l2pf(const void* p)
{ asm volatile("prefetch.global.L2 [%0];" :: "l"(p)); }

// select component s (0..3) of a float4 without local-memory indexing
__device__ __forceinline__ float sel4(float4 v, int s)
{
    float ab = (s & 1) ? v.y : v.x;
    float cd = (s & 1) ? v.w : v.z;
    return (s & 2) ? cd : ab;
}

// ---------------- kernel 1: sequence lengths (mask is a prefix; len in [1024,2048]) ----
__global__ void scan_len(const int* __restrict__ tags)
{
    int w    = blockIdx.x * 8 + (threadIdx.x >> 5);
    int lane = threadIdx.x & 31;
    const int4* p = (const int4*)(tags + (size_t)w * L_ + 1024);
    int firstz = 1024;
    #pragma unroll
    for (int k = 0; k < 8; k++) {
        int4 v = p[k * 32 + lane];
        int base = (k * 32 + lane) * 4;
        if (v.w == 0) firstz = min(firstz, base + 3);
        if (v.z == 0) firstz = min(firstz, base + 2);
        if (v.y == 0) firstz = min(firstz, base + 1);
        if (v.x == 0) firstz = min(firstz, base + 0);
    }
    firstz = __reduce_min_sync(FULL_MASK, firstz);
    if (lane == 0) g_len[w] = 1024 + firstz;
}

// ---------------- kernel 2: length-sorted order via all-pairs rank (deterministic) ----
__global__ void rank_order()
{
    __shared__ int s_len[B_];
    for (int i = threadIdx.x; i < B_; i += blockDim.x) s_len[i] = g_len[i];
    __syncthreads();
    int b   = blockIdx.x * blockDim.x + threadIdx.x;   // 16x128 -> 2048 threads
    int myl = s_len[b];
    int r = 0;
    #pragma unroll 8
    for (int i = 0; i < B_; i++) {
        int li = s_len[i];
        r += (li < myl) || (li == myl && i < b);
    }
    g_order[r] = b;
}

// ---------------- kernel 3: fwd/bwd chains, 2 lanes per chain, 16 chains per warp ----
__global__ void crf_chains(const float* __restrict__ em, const float* __restrict__ trans,
                           const float* __restrict__ startT, const float* __restrict__ endT,
                           const int* __restrict__ tags)
{
    __shared__ float s_tr[64];
    int lane = threadIdx.x;                            // block = 1 warp
    s_tr[lane]      = trans[lane];
    s_tr[lane + 32] = trans[lane + 32];
    __syncwarp();

    int h  = lane & 1;                                 // which half of the state vector
    int pr = lane >> 1;                                // chain index within warp
    int gw = blockIdx.x;                               // 0..255
    bool is_bwd = (gw >= 128);
    int b   = g_order[(gw & 127) * 16 + pr];
    int len = g_len[b];
    int mid = len >> 1;                                // fwd: t=0..mid, bwd: mid+1..len-1
    int o0 = 4 * h, p0 = 4 - 4 * h;                    // own / partner state base

    const float* emB = em + (size_t)b * (L_ * 8) + o0; // own-half emission base
    const int*   tgB = tags + (size_t)b * L_;

    float W[4][4], V[4][4];                            // E slices (own-src, partner-src)
    float a[4], c = 0.0f, num = 0.0f;
    float4 cur0, cur1, cur2, cur3;

    if (!is_bwd) {
        // ==== FORWARD: alpha_t[j] = (sum_k alpha[k] E[k][j]) * exp(em_t[j]) ====
        #pragma unroll
        for (int k = 0; k < 4; k++)
            #pragma unroll
            for (int o = 0; o < 4; o++) {
                W[k][o] = fexp(s_tr[(o0 + k) * 8 + o0 + o]);
                V[k][o] = fexp(s_tr[(p0 + k) * 8 + o0 + o]);
            }
        float4 em0 = __ldg((const float4*)emB);
        a[0] = fexp(__ldg(&startT[o0 + 0]) + em0.x);
        a[1] = fexp(__ldg(&startT[o0 + 1]) + em0.y);
        a[2] = fexp(__ldg(&startT[o0 + 2]) + em0.z);
        a[3] = fexp(__ldg(&startT[o0 + 3]) + em0.w);
        int s_prev = __ldg(&tgB[0]) - 1;               // len>=1024 => tag0 != 0
        if ((s_prev >> 2) == h) num = __ldg(&startT[s_prev]) + sel4(em0, s_prev & 3);

        int Tw = __reduce_max_sync(FULL_MASK, mid);    // warp-max active step
        cur0 = __ldg((const float4*)(emB + 1 * 8));
        cur1 = __ldg((const float4*)(emB + 2 * 8));
        cur2 = __ldg((const float4*)(emB + 3 * 8));
        cur3 = __ldg((const float4*)(emB + 4 * 8));
        int tgc = __ldg(&tgB[1]);
        int rc2 = 2;                                   // renorm every 2 blocks (8 steps)
        for (int t = 1; t <= Tw; t += 4) {
            // next em block (indices <= Tw+7 <= 1030: in-tensor; garbage rows only
            // ever reach inactive chains whose state is frozen)
            float4 nx0 = __ldg((const float4*)(emB + (size_t)(t + 4) * 8));
            float4 nx1 = __ldg((const float4*)(emB + (size_t)(t + 5) * 8));
            float4 nx2 = __ldg((const float4*)(emB + (size_t)(t + 6) * 8));
            float4 nx3 = __ldg((const float4*)(emB + (size_t)(t + 7) * 8));
            l2pf(emB + (size_t)(t + 20) * 8);
            l2pf(&tgB[t + 32]);
            #pragma unroll
            for (int i = 0; i < 4; i++) {
                float4 emc = (i == 0) ? cur0 : (i == 1) ? cur1 : (i == 2) ? cur2 : cur3;
                int tt = t + i;
                int tgn = __ldg(&tgB[min(tt + 1, Tw + 1)]);
                float ex0 = fexp(emc.x), ex1 = fexp(emc.y);
                float ex2 = fexp(emc.z), ex3 = fexp(emc.w);
                float xs0 = __shfl_xor_sync(FULL_MASK, a[0], 1);
                float xs1 = __shfl_xor_sync(FULL_MASK, a[1], 1);
                float xs2 = __shfl_xor_sync(FULL_MASK, a[2], 1);
                float xs3 = __shfl_xor_sync(FULL_MASK, a[3], 1);
                float o_[4];
                #pragma unroll
                for (int o = 0; o < 4; o++) {
                    float so = a[0] * W[0][o];
                    so = fmaf(a[1], W[1][o], so);
                    so = fmaf(a[2], W[2][o], so);
                    so = fmaf(a[3], W[3][o], so);
                    float sx = xs0 * V[0][o];
                    sx = fmaf(xs1, V[1][o], sx);
                    sx = fmaf(xs2, V[2][o], sx);
                    sx = fmaf(xs3, V[3][o], sx);
                    o_[o] = so + sx;
                }
                bool act = (tt <= mid);
                int st = tgc - 1;
                if (act) {
                    a[0] = o_[0] * ex0; a[1] = o_[1] * ex1;
                    a[2] = o_[2] * ex2; a[3] = o_[3] * ex3;
                    if ((st >> 2) == h) num += s_tr[(s_prev << 3) | st] + sel4(emc, st & 3);
                    s_prev = st;
                }
                tgc = tgn;
            }
            if (--rc2 == 0) {
                rc2 = 2;
                float a0e = __shfl_sync(FULL_MASK, a[0], 0, 2);   // even lane's a[0]
                int eb = __float_as_int(a0e) & 0x7f800000;
                c += (float)((eb >> 23) - 127);
                float sc = __int_as_float(0x7f000000 - eb);       // exact 2^{-e}
                a[0] *= sc; a[1] *= sc; a[2] *= sc; a[3] *= sc;
            }
            cur0 = nx0; cur1 = nx1; cur2 = nx2; cur3 = nx3;
        }
        g_af[b * 8 + o0 + 0] = a[0]; g_af[b * 8 + o0 + 1] = a[1];
        g_af[b * 8 + o0 + 2] = a[2]; g_af[b * 8 + o0 + 3] = a[3];
        num += __shfl_xor_sync(FULL_MASK, num, 1);
        if (h == 0) { g_cf[b] = c; g_nf[b] = num; }
    } else {
        // ==== BACKWARD: beta_{t-1}[i] = sum_j E[i][j] * exp(em_t[j]) * beta_t[j] ====
        #pragma unroll
        for (int k = 0; k < 4; k++)
            #pragma unroll
            for (int o = 0; o < 4; o++) {
                W[k][o] = fexp(s_tr[(o0 + o) * 8 + o0 + k]);
                V[k][o] = fexp(s_tr[(o0 + o) * 8 + p0 + k]);
            }
        a[0] = fexp(__ldg(&endT[o0 + 0]));
        a[1] = fexp(__ldg(&endT[o0 + 1]));
        a[2] = fexp(__ldg(&endT[o0 + 2]));
        a[3] = fexp(__ldg(&endT[o0 + 3]));
        int s_hi = __ldg(&tgB[len - 1]) - 1;
        if ((s_hi >> 2) == h) num = __ldg(&endT[s_hi]);

        int Sw = __reduce_max_sync(FULL_MASK, len - 1 - mid);
        int t1 = len - 1;
        int lo = mid + 1;                              // lowest active t
        cur0 = __ldg((const float4*)(emB + (size_t)max(t1 - 0, lo) * 8));
        cur1 = __ldg((const float4*)(emB + (size_t)max(t1 - 1, lo) * 8));
        cur2 = __ldg((const float4*)(emB + (size_t)max(t1 - 2, lo) * 8));
        cur3 = __ldg((const float4*)(emB + (size_t)max(t1 - 3, lo) * 8));
        int tgc = __ldg(&tgB[t1 - 1]);                 // tag at t-1 for first step
        int rc2 = 2;
        for (int s = 0; s < Sw; s += 4) {
            int tb = t1 - s;
            float4 nx0 = __ldg((const float4*)(emB + (size_t)max(tb - 4, lo) * 8));
            float4 nx1 = __ldg((const float4*)(emB + (size_t)max(tb - 5, lo) * 8));
            float4 nx2 = __ldg((const float4*)(emB + (size_t)max(tb - 6, lo) * 8));
            float4 nx3 = __ldg((const float4*)(emB + (size_t)max(tb - 7, lo) * 8));
            l2pf(emB + (size_t)max(tb - 20, lo) * 8);
            l2pf(&tgB[max(tb - 32, lo - 1)]);
            #pragma unroll
            for (int i = 0; i < 4; i++) {
                float4 emc = (i == 0) ? cur0 : (i == 1) ? cur1 : (i == 2) ? cur2 : cur3;
                int t = tb - i;
                bool act = (t >= lo);
                int tgn = __ldg(&tgB[max(t - 2, lo - 1)]);
                float q0 = a[0] * fexp(emc.x), q1 = a[1] * fexp(emc.y);
                float q2 = a[2] * fexp(emc.z), q3 = a[3] * fexp(emc.w);
                float xs0 = __shfl_xor_sync(FULL_MASK, q0, 1);
                float xs1 = __shfl_xor_sync(FULL_MASK, q1, 1);
                float xs2 = __shfl_xor_sync(FULL_MASK, q2, 1);
                float xs3 = __shfl_xor_sync(FULL_MASK, q3, 1);
                float o_[4];
                #pragma unroll
                for (int o = 0; o < 4; o++) {
                    float so = q0 * W[0][o];
                    so = fmaf(q1, W[1][o], so);
                    so = fmaf(q2, W[2][o], so);
                    so = fmaf(q3, W[3][o], so);
                    float sx = xs0 * V[0][o];
                    sx = fmaf(xs1, V[1][o], sx);
                    sx = fmaf(xs2, V[2][o], sx);
                    sx = fmaf(xs3, V[3][o], sx);
                    o_[o] = so + sx;
                }
                if (act) {
                    a[0] = o_[0]; a[1] = o_[1]; a[2] = o_[2]; a[3] = o_[3];
                    int sl = tgc - 1;
                    if ((s_hi >> 2) == h) num += s_tr[(sl << 3) | s_hi] + sel4(emc, s_hi & 3);
                    s_hi = sl;
                }
                tgc = tgn;
            }
            if (--rc2 == 0) {
                rc2 = 2;
                float a0e = __shfl_sync(FULL_MASK, a[0], 0, 2);
                int eb = __float_as_int(a0e) & 0x7f800000;
                c += (float)((eb >> 23) - 127);
                float sc = __int_as_float(0x7f000000 - eb);
                a[0] *= sc; a[1] *= sc; a[2] *= sc; a[3] *= sc;
            }
            cur0 = nx0; cur1 = nx1; cur2 = nx2; cur3 = nx3;
        }
        g_w[b * 8 + o0 + 0] = a[0]; g_w[b * 8 + o0 + 1] = a[1];
        g_w[b * 8 + o0 + 2] = a[2]; g_w[b * 8 + o0 + 3] = a[3];
        num += __shfl_xor_sync(FULL_MASK, num, 1);
        if (h == 0) { g_cb[b] = c; g_nb[b] = num; }
    }
}

// ---------------- kernel 4: combine halves + deterministic mean ----------------
__global__ void crf_combine(float* __restrict__ out)
{
    __shared__ float sb[1024];
    int tid = threadIdx.x;
    float acc = 0.0f;
    #pragma unroll
    for (int it = 0; it < 2; it++) {
        int b = tid + it * 1024;                       // fixed per-thread order
        const float4* pa = (const float4*)&g_af[b * 8];
        const float4* pw = (const float4*)&g_w[b * 8];
        float4 a0 = pa[0], a1 = pa[1], w0 = pw[0], w1 = pw[1];
        float Z = a0.x * w0.x + a0.y * w0.y + a0.z * w0.z + a0.w * w0.w
                + a1.x * w1.x + a1.y * w1.y + a1.z * w1.z + a1.w * w1.w;
        acc += g_nf[b] + g_nb[b] - LN2_F * (g_cf[b] + g_cb[b] + __log2f(Z));
    }
    sb[tid] = acc;
    __syncthreads();
    for (int k = 512; k > 0; k >>= 1) {
        if (tid < k) sb[tid] += sb[tid + k];
        __syncthreads();
    }
    if (tid == 0) out[0] = -sb[0] * (1.0f / (float)B_);
}

extern "C" void kernel_launch(void* const* d_in, const int* in_sizes, int n_in,
                              void* d_out, int out_size)
{
    const float* em    = (const float*)d_in[0];   // (B, L, T) f32
    const float* trans = (const float*)d_in[1];   // (T, T)    f32
    const float* st    = (const float*)d_in[2];   // (T,)      f32
    const float* en    = (const float*)d_in[3];   // (T,)      f32
    const int*   tags  = (const int*)  d_in[4];   // (B, L)    int32

    scan_len   <<<256, 256>>>(tags);
    rank_order <<<16, 128>>>();
    crf_chains <<<256, 32>>>(em, trans, st, en, tags);
    crf_combine<<<1, 1024>>>((float*)d_out);
}

// round 14
// speedup vs baseline: 2.9804x; 1.9272x over previous
#include <cuda_runtime.h>
#include <cstdint>

#define FULL_MASK 0xFFFFFFFFu

constexpr int B_ = 2048;
constexpr int L_ = 2048;
constexpr int T_ = 8;
constexpr float LOG2E_F = 1.4426950408889634f;
constexpr float LN2_F   = 0.6931471805599453f;

// device scratch (no allocation allowed)
__device__ int   g_len[B_];
__device__ int   g_order[B_];
__device__ __align__(16) float g_alpha[B_ * 8];
__device__ __align__(16) float g_beta [B_ * 8];
__device__ float g_cf[B_], g_cb[B_], g_numf[B_], g_numb[B_];

__device__ __forceinline__ float fast_exp2(float x)
{
    float r;
    asm("ex2.approx.ftz.f32 %0, %1;" : "=f"(r) : "f"(x));
    return r;
}
__device__ __forceinline__ float fast_expe(float x) { return fast_exp2(x * LOG2E_F); }

__device__ __forceinline__ void l2_prefetch(const void* p)
{
    asm volatile("prefetch.global.L2 [%0];" :: "l"(p));
}

// Cheap exact power-of-two renorm: scale group by 2^-e(lane0).
__device__ __forceinline__ void grp_renorm_l0(float& a, float& c)
{
    float a0 = __shfl_sync(FULL_MASK, a, 0, 8);
    int eb = __float_as_int(a0) & 0x7f800000;
    c += (float)((eb >> 23) - 127);
    a *= __int_as_float(0x7f000000 - eb);      // exact 2^{-e}
}

// ---------------- kernel 1: sequence lengths (mask is a prefix; len in [1024,2048]) ----
__global__ void scan_len(const int* __restrict__ tags)
{
    int w    = blockIdx.x * 8 + (threadIdx.x >> 5);
    int lane = threadIdx.x & 31;
    const int4* p = (const int4*)(tags + (size_t)w * L_ + 1024);
    int firstz = 1024;
    #pragma unroll
    for (int k = 0; k < 8; k++) {
        int4 v = p[k * 32 + lane];
        int base = (k * 32 + lane) * 4;
        if (v.w == 0) firstz = min(firstz, base + 3);
        if (v.z == 0) firstz = min(firstz, base + 2);
        if (v.y == 0) firstz = min(firstz, base + 1);
        if (v.x == 0) firstz = min(firstz, base + 0);
    }
    firstz = __reduce_min_sync(FULL_MASK, firstz);
    if (lane == 0) g_len[w] = 1024 + firstz;
}

// ---------------- kernel 2: length-sorted order via all-pairs rank (deterministic) ----
__global__ void rank_order()
{
    __shared__ int s_len[B_];
    for (int i = threadIdx.x; i < B_; i += blockDim.x) s_len[i] = g_len[i];
    __syncthreads();
    int b   = blockIdx.x * blockDim.x + threadIdx.x;   // 16x128 -> 2048 threads
    int myl = s_len[b];
    int r = 0;
    #pragma unroll 8
    for (int i = 0; i < B_; i++) {
        int li = s_len[i];
        r += (li < myl) || (li == myl && i < b);
    }
    g_order[r] = b;
}

// ---------------- kernel 3: main forward/backward recursions (BRANCHLESS core) ----
__global__ __launch_bounds__(128)
void crf_main(const float* __restrict__ em,
              const float* __restrict__ trans,
              const float* __restrict__ startT,
              const float* __restrict__ endT,
              const int*   __restrict__ tags)
{
    __shared__ float s_trans[T_ * T_];
    int tid = threadIdx.x;
    if (tid < 64) s_trans[tid] = trans[tid];
    __syncthreads();

    int lane = tid & 31;
    int j    = lane & 7;
    int W    = blockIdx.x * 4 + (tid >> 5);            // 0..1023
    bool is_bwd = (W >= 512);
    int  idx    = is_bwd ? (W - 512) : W;

    int b   = g_order[idx * 4 + (lane >> 3)];
    int len = g_len[b];
    int mid = len >> 1;                                // fwd: t=0..mid, bwd: (mid, len-1]

    const float* emb = em   + (size_t)b * (L_ * T_) + j;
    const int*   tgb = tags + (size_t)b * L_;

    float emA[8], exA[8], emB[8];
    int   tgA[8], tgB[8];

    if (!is_bwd) {
        // ======== FORWARD: alpha_t = ex_t ⊙ (E^T alpha_{t-1}),  t = 1..mid ========
        float Er[8];
        #pragma unroll
        for (int k = 0; k < 8; k++) Er[k] = fast_expe(s_trans[((j ^ k) << 3) | j]);

        int lim  = mid;
        int m_hi = __reduce_max_sync(FULL_MASK, mid);

        int   s_prev = tgb[0] - 1;                     // len>=1024 => tag0 != 0
        float em0    = emb[0];
        float a      = fast_expe(startT[j] + em0);
        float c      = 0.0f;
        float num    = (j == s_prev) ? (startT[j] + em0) : 0.0f;

        #pragma unroll
        for (int u = 0; u < 8; u++) { emA[u] = emb[(1 + u) * 8]; tgA[u] = tgb[1 + u]; }
        #pragma unroll
        for (int u = 0; u < 8; u++) { emB[u] = emb[(9 + u) * 8]; tgB[u] = tgb[9 + u]; }
        #pragma unroll
        for (int u = 0; u < 8; u++) exA[u] = fast_expe(emA[u]);

        for (int t = 1; t <= m_hi; t += 8) {
            l2_prefetch(&emb[(t + 24 + j) * 8]);
            if (j == 0) l2_prefetch(&tgb[t + 24]);
            #pragma unroll
            for (int u = 0; u < 8; u++) {
                int tt = t + u;
                float x1 = __shfl_xor_sync(FULL_MASK, a, 1, 8);
                float x2 = __shfl_xor_sync(FULL_MASK, a, 2, 8);
                float x3 = __shfl_xor_sync(FULL_MASK, a, 3, 8);
                float x4 = __shfl_xor_sync(FULL_MASK, a, 4, 8);
                float x5 = __shfl_xor_sync(FULL_MASK, a, 5, 8);
                float x6 = __shfl_xor_sync(FULL_MASK, a, 6, 8);
                float x7 = __shfl_xor_sync(FULL_MASK, a, 7, 8);
                float s1 = fmaf(x1, Er[1], a  * Er[0]);
                float s2 = fmaf(x3, Er[3], x2 * Er[2]);
                float s3 = fmaf(x5, Er[5], x4 * Er[4]);
                float s4 = fmaf(x7, Er[7], x6 * Er[6]);
                float s  = (s1 + s2) + (s3 + s4);
                // ---- branchless update ----
                bool  act    = (tt <= lim);
                int   s_t    = tgA[u] - 1;
                float a_cand = s * exA[u];
                a = act ? a_cand : a;                              // FSEL (exact freeze)
                float addv = s_trans[(s_prev << 3) | j] + emA[u];  // uncond LDS+FADD
                num += (act && (j == s_t)) ? addv : 0.0f;          // FSEL+FADD
                s_prev = act ? s_t : s_prev;                       // SEL
            }
            grp_renorm_l0(a, c);
            #pragma unroll
            for (int u = 0; u < 8; u++) { emA[u] = emB[u]; tgA[u] = tgB[u]; }
            #pragma unroll
            for (int u = 0; u < 8; u++) {              // load block t+16 (max 1047 < 2048)
                emB[u] = emb[(t + 16 + u) * 8]; tgB[u] = tgb[t + 16 + u];
            }
            #pragma unroll
            for (int u = 0; u < 8; u++) exA[u] = fast_expe(emA[u]);
        }
        num += __shfl_xor_sync(FULL_MASK, num, 1, 8);
        num += __shfl_xor_sync(FULL_MASK, num, 2, 8);
        num += __shfl_xor_sync(FULL_MASK, num, 4, 8);
        g_alpha[b * 8 + j] = a;
        if (j == 0) { g_cf[b] = c; g_numf[b] = num; }
    } else {
        // ======== BACKWARD: beta_{t-1} = E (ex_t ⊙ beta_t),  t = len-1 .. mid+1 ========
        float ErR[8];
        #pragma unroll
        for (int k = 0; k < 8; k++) ErR[k] = fast_expe(s_trans[(j << 3) | (j ^ k)]);

        float endj = endT[j];
        float beta = fast_expe(endj);
        float c = 0.0f, num = 0.0f;
        int   s_succ = 0;

        int t0   = __reduce_max_sync(FULL_MASK, len) - 1;
        int tmin = __reduce_min_sync(FULL_MASK, mid) + 1;

        #pragma unroll
        for (int u = 0; u < 8; u++) { int q = t0 - u;     emA[u] = emb[q * 8]; tgA[u] = tgb[q]; }
        #pragma unroll
        for (int u = 0; u < 8; u++) { int q = t0 - 8 - u; emB[u] = emb[q * 8]; tgB[u] = tgb[q]; }
        #pragma unroll
        for (int u = 0; u < 8; u++) exA[u] = fast_expe(emA[u]);

        for (int t = t0; t >= tmin; t -= 8) {
            l2_prefetch(&emb[(t - 24 - j) * 8]);
            if (j == 0) l2_prefetch(&tgb[t - 24]);
            #pragma unroll
            for (int u = 0; u < 8; u++) {
                int tt = t - u;
                float p  = beta * exA[u];
                float x1 = __shfl_xor_sync(FULL_MASK, p, 1, 8);
                float x2 = __shfl_xor_sync(FULL_MASK, p, 2, 8);
                float x3 = __shfl_xor_sync(FULL_MASK, p, 3, 8);
                float x4 = __shfl_xor_sync(FULL_MASK, p, 4, 8);
                float x5 = __shfl_xor_sync(FULL_MASK, p, 5, 8);
                float x6 = __shfl_xor_sync(FULL_MASK, p, 6, 8);
                float x7 = __shfl_xor_sync(FULL_MASK, p, 7, 8);
                float s1 = fmaf(x1, ErR[1], p  * ErR[0]);
                float s2 = fmaf(x3, ErR[3], x2 * ErR[2]);
                float s3 = fmaf(x5, ErR[5], x4 * ErR[4]);
                float s4 = fmaf(x7, ErR[7], x6 * ErR[6]);
                float s  = (s1 + s2) + (s3 + s4);
                // ---- branchless update ----
                bool  act = (tt > mid) && (tt < len);
                int   s_t = tgA[u] - 1;
                beta = act ? s : beta;                             // FSEL
                float tr   = s_trans[(j << 3) | s_succ];           // uncond LDS (old s_succ)
                float addv = emA[u] + ((tt == len - 1) ? endj : tr);
                num += (act && (j == s_t)) ? addv : 0.0f;
                s_succ = act ? s_t : s_succ;                       // SEL
            }
            grp_renorm_l0(beta, c);
            #pragma unroll
            for (int u = 0; u < 8; u++) { emA[u] = emB[u]; tgA[u] = tgB[u]; }
            #pragma unroll
            for (int u = 0; u < 8; u++) {              // load block t-16.. (min q >= 467 > 0)
                int q = t - 16 - u;
                emB[u] = emb[q * 8]; tgB[u] = tgb[q];
            }
            #pragma unroll
            for (int u = 0; u < 8; u++) exA[u] = fast_expe(emA[u]);
        }
        // missing transition pair (s_mid -> s_{mid+1}); s_succ == s_{mid+1} here
        int s_m = tgb[mid] - 1;
        if (j == s_m) num += s_trans[(j << 3) | s_succ];

        num += __shfl_xor_sync(FULL_MASK, num, 1, 8);
        num += __shfl_xor_sync(FULL_MASK, num, 2, 8);
        num += __shfl_xor_sync(FULL_MASK, num, 4, 8);
        g_beta[b * 8 + j] = beta;
        if (j == 0) { g_cb[b] = c; g_numb[b] = num; }
    }
}

// ---------------- kernel 4: combine halves + deterministic mean ----------------
__global__ void crf_combine(float* __restrict__ out)
{
    __shared__ float sb[1024];
    int tid = threadIdx.x;
    float acc = 0.0f;
    #pragma unroll
    for (int it = 0; it < 2; it++) {
        int b = tid + it * 1024;                       // fixed per-thread order
        const float4* pa = (const float4*)&g_alpha[b * 8];
        const float4* pw = (const float4*)&g_beta[b * 8];
        float4 a0 = pa[0], a1 = pa[1], w0 = pw[0], w1 = pw[1];
        float Z = a0.x * w0.x + a0.y * w0.y + a0.z * w0.z + a0.w * w0.w
                + a1.x * w1.x + a1.y * w1.y + a1.z * w1.z + a1.w * w1.w;
        acc += g_numf[b] + g_numb[b] - LN2_F * (g_cf[b] + g_cb[b] + __log2f(Z));
    }
    sb[tid] = acc;
    __syncthreads();
    for (int k = 512; k > 0; k >>= 1) {
        if (tid < k) sb[tid] += sb[tid + k];
        __syncthreads();
    }
    if (tid == 0) out[0] = -sb[0] * (1.0f / (float)B_);
}

extern "C" void kernel_launch(void* const* d_in, const int* in_sizes, int n_in,
                              void* d_out, int out_size)
{
    const float* em    = (const float*)d_in[0];   // (B, L, T) f32
    const float* trans = (const float*)d_in[1];   // (T, T)    f32
    const float* st    = (const float*)d_in[2];   // (T,)      f32
    const float* en    = (const float*)d_in[3];   // (T,)      f32
    const int*   tags  = (const int*)  d_in[4];   // (B, L)    int32

    scan_len   <<<256, 256>>>(tags);
    rank_order <<<16, 128>>>();
    crf_main   <<<256, 128>>>(em, trans, st, en, tags);
    crf_combine<<<1, 1024>>>((float*)d_out);
}